// round 12
// baseline (speedup 1.0000x reference)
#include <cuda_runtime.h>
#include <cuda_bf16.h>
#include <cstdint>

// ---------------- problem constants ----------------
#define B_ 256
#define T_ 512
#define D_ 64
#define H_ 512
#define G_ 2048
#define NCTA 128
#define NTHR 544          // 16 compute warps + 1 producer warp
#define NCW 16
#define HC 4              // h-columns per CTA (16 gate cols)
#define NCOL 16           // gate cols per CTA
#define FLAGTGT 16u       // CTAs producing each 64-col chunk
#define RD 4              // ring depth (32KB half-row items)
#define BROW 1168         // padded B row bytes (9*128 + 16)
#define BPLANE (NCOL * BROW)

// ---------------- dynamic SMEM layout (bytes) ----------------
#define SM_MBF 0                         // RD full barriers
#define SM_MBE 64                        // RD empty barriers
#define SM_BIAS 128
#define SM_A 1024                        // ring: 4 x 32768 (hi 16K + lo 16K)
#define SM_B (SM_A + RD * 32768)         // 2 planes x BPLANE
#define SMEM_BYTES (SM_B + 2 * BPLANE)   // 169472

// ---------------- persistent device state ----------------
// h K-blocked swizzled, TRIPLE buffered: [buf][plane][kc][row 256][64]
__device__ __align__(128) __nv_bfloat16 g_hA[3][2][8][256][64];
// x per-step K-blocked swizzled: [plane][t][row 256][64]
__device__ __align__(128) __nv_bfloat16 g_xA[2][T_][256][64];
__device__ unsigned g_flag[T_ + 1][8];   // readiness of input chunk kc at step t
__device__ unsigned g_count, g_gen;

// ---------------- math helpers ----------------
__device__ __forceinline__ float softplus_(float r) {
    return (r > 15.f) ? r : log1pf(expf(r));
}
__device__ __forceinline__ float sample_(float mu, float rho, float eps) {
    return mu + softplus_(rho) * eps;
}
__device__ __forceinline__ float sigmoid_(float x) {
    return __fdividef(1.f, 1.f + __expf(-x));
}
__device__ __forceinline__ float tanh_(float x) {
    return __fdividef(2.f, 1.f + __expf(-2.f * x)) - 1.f;
}

// ---------------- PTX helpers ----------------
__device__ __forceinline__ uint32_t smem_u32_(const void* p) {
    uint32_t a;
    asm("{ .reg .u64 t; cvta.to.shared.u64 t, %1; cvt.u32.u64 %0, t; }"
        : "=r"(a) : "l"(p));
    return a;
}
__device__ __forceinline__ void mbar_init_(uint32_t a, uint32_t cnt) {
    asm volatile("mbarrier.init.shared.b64 [%0], %1;" :: "r"(a), "r"(cnt) : "memory");
}
__device__ __forceinline__ void mbar_inval_(uint32_t a) {
    asm volatile("mbarrier.inval.shared.b64 [%0];" :: "r"(a) : "memory");
}
__device__ __forceinline__ void mbar_expect_tx_(uint32_t a, uint32_t bytes) {
    asm volatile("mbarrier.arrive.expect_tx.shared.b64 _, [%0], %1;"
                 :: "r"(a), "r"(bytes) : "memory");
}
__device__ __forceinline__ void mbar_arrive_(uint32_t a) {
    asm volatile("mbarrier.arrive.shared.b64 _, [%0];" :: "r"(a) : "memory");
}
__device__ __forceinline__ void mbar_wait_(uint32_t a, uint32_t parity) {
    uint32_t done;
    asm volatile(
        "{\n\t.reg .pred p;\n\t"
        "mbarrier.try_wait.parity.acquire.cta.shared::cta.b64 p, [%1], %2;\n\t"
        "selp.b32 %0, 1, 0, p;\n\t}"
        : "=r"(done) : "r"(a), "r"(parity) : "memory");
    if (!done) {
        asm volatile(
            "{\n\t.reg .pred P1;\n\t"
            "W_%=:\n\t"
            "mbarrier.try_wait.parity.acquire.cta.shared::cta.b64 P1, [%0], %1, 0x989680;\n\t"
            "@P1 bra.uni D_%=;\n\t"
            "bra.uni W_%=;\n\t"
            "D_%=:\n\t}"
            :: "r"(a), "r"(parity) : "memory");
    }
}
__device__ __forceinline__ void bulk_g2s_(uint32_t dst, const void* src,
                                          uint32_t bytes, uint32_t mbar) {
    asm volatile(
        "cp.async.bulk.shared::cluster.global.mbarrier::complete_tx::bytes "
        "[%0], [%1], %2, [%3];"
        :: "r"(dst), "l"(src), "r"(bytes), "r"(mbar) : "memory");
}
__device__ __forceinline__ void flag_wait_(const unsigned* p) {
    unsigned v;
    do {
        asm volatile("ld.global.cg.u32 %0, [%1];" : "=r"(v) : "l"(p));
        if (v >= FLAGTGT) break;
        __nanosleep(16);
    } while (1);
    __threadfence();
}

#define LDM4(R, A) \
    asm volatile("ldmatrix.sync.aligned.m8n8.x4.shared.b16 {%0,%1,%2,%3}, [%4];" \
        : "=r"((R)[0]), "=r"((R)[1]), "=r"((R)[2]), "=r"((R)[3]) : "r"(A))

#define MMA(Cf, Af, Bf0, Bf1) \
    asm volatile("mma.sync.aligned.m16n8k16.row.col.f32.bf16.bf16.f32 " \
        "{%0,%1,%2,%3}, {%4,%5,%6,%7}, {%8,%9}, {%0,%1,%2,%3};" \
        : "+f"((Cf)[0]), "+f"((Cf)[1]), "+f"((Cf)[2]), "+f"((Cf)[3]) \
        : "r"((Af)[0]), "r"((Af)[1]), "r"((Af)[2]), "r"((Af)[3]), \
          "r"(Bf0), "r"(Bf1))

extern "C" __global__ void bar_init_kernel() {
    const int tid = threadIdx.x;
    unsigned* f = (unsigned*)g_flag;
    for (int i = tid; i < (T_ + 1) * 8; i += blockDim.x)
        f[i] = (i < 8) ? FLAGTGT : 0u;     // step-0 input (zeros) pre-ready
    if (tid == 0) { g_count = 0; g_gen = 0; }
}

// ---------------- one-shot grid barrier (startup only) ----------------
__device__ __forceinline__ void grid_sync_(unsigned target) {
    __syncthreads();
    if (threadIdx.x == 0) {
        __threadfence();
        unsigned a = atomicAdd(&g_count, 1u);
        if (a == NCTA - 1) {
            g_count = 0;
            __threadfence();
            atomicExch(&g_gen, target);
        } else {
            unsigned g;
            do {
                asm volatile("ld.global.cg.u32 %0, [%1];" : "=r"(g) : "l"(&g_gen));
                if (g >= target) break;
                __nanosleep(32);
            } while (1);
        }
        __threadfence();
    }
    __syncthreads();
}

// gate/hcol mapping within the 16 local cols (4 gates x 4 h-cols, no shuffles)
__device__ __forceinline__ int colmap_(int n, int j0) {
    int gate = ((n >> 3) << 1) | (n & 1);
    int hcol = (n >> 1) & 3;
    return gate * H_ + j0 + hcol;
}

// ---------------- main persistent kernel ----------------
extern "C" __global__ void __launch_bounds__(NTHR, 1)
lstm_hmma(const float* __restrict__ x,
          const float* __restrict__ wih_mu, const float* __restrict__ wih_rho,
          const float* __restrict__ wih_eps,
          const float* __restrict__ whh_mu, const float* __restrict__ whh_rho,
          const float* __restrict__ whh_eps,
          const float* __restrict__ b_mu,   const float* __restrict__ b_rho,
          const float* __restrict__ b_eps,
          const float* __restrict__ lin_w,  const float* __restrict__ lin_b,
          float* __restrict__ out)
{
    extern __shared__ char smem[];
    const uint32_t sbase = smem_u32_(smem);
    float* bias_s = (float*)(smem + SM_BIAS);

    const int tid  = threadIdx.x;
    const int lane = tid & 31;
    const int w    = tid >> 5;          // 0..15 compute, 16 producer
    const int cta  = blockIdx.x;
    const int j0   = cta * HC;          // first h-col
    const int kc0  = j0 >> 6;           // h chunk our cols land in

    if (tid == 0) {
        #pragma unroll
        for (int s = 0; s < RD; s++) {
            mbar_init_(sbase + SM_MBF + s * 8, 1);
            mbar_init_(sbase + SM_MBE + s * 8, 8);   // 8 warps per row-half
        }
    }

    // ---- sample W into SMEM B planes: rows n (16), cols k (576), padded ----
    for (int idx = tid; idx < NCOL * 576; idx += NTHR) {
        int n = idx / 576, k = idx - n * 576;
        int col = colmap_(n, j0);
        float wv;
        if (k < 512) {
            int gi = k * G_ + col;
            wv = sample_(whh_mu[gi], whh_rho[gi], whh_eps[gi]);
        } else {
            int gi = (k - 512) * G_ + col;
            wv = sample_(wih_mu[gi], wih_rho[gi], wih_eps[gi]);
        }
        __nv_bfloat16 hi = __float2bfloat16(wv);
        __nv_bfloat16 lo = __float2bfloat16(wv - __bfloat162float(hi));
        *(__nv_bfloat16*)(smem + SM_B + 0 * BPLANE + n * BROW + k * 2) = hi;
        *(__nv_bfloat16*)(smem + SM_B + 1 * BPLANE + n * BROW + k * 2) = lo;
    }
    if (tid < NCOL) {
        int col = colmap_(tid, j0);
        bias_s[tid] = sample_(b_mu[col], b_rho[col], b_eps[col]);
    }

    // ---- build swizzled x planes + zero h buf0 (grid-wide striped) ----
    {
        const int gtid = cta * NTHR + tid;
        const int gn = NCTA * NTHR;
        for (int i = gtid; i < B_ * T_ * D_; i += gn) {
            int d = i & 63, r = i >> 6;
            int t = r & 511, b = r >> 9;            // x is [b][t][d]
            float v = __ldg(&x[i]);
            __nv_bfloat16 hi = __float2bfloat16(v);
            __nv_bfloat16 lo = __float2bfloat16(v - __bfloat162float(hi));
            uint32_t off = ((uint32_t)t * 256 + (uint32_t)b) * 128 +
                           (((uint32_t)d * 2) ^ (((uint32_t)b & 7) << 4));
            *(__nv_bfloat16*)((char*)g_xA + off) = hi;
            *(__nv_bfloat16*)((char*)g_xA + (size_t)T_ * 32768 + off) = lo;
        }
        uint32_t* hz = (uint32_t*)g_hA;             // buf0, both planes
        for (int i = gtid; i < 131072; i += gn) hz[i] = 0u;
    }

    grid_sync_(1);

    // ================= producer warp: lane s owns ring slot s =================
    // 18 items/step: item j -> pair p=j>>1 (p=0: x, p>=1: chunk (kc0+p-1)&7),
    // half hf=j&1 (rows hf*128..+128). slot = itg & 3 == lane.
    if (w == NCW) {
        if (lane < RD) {
            const uint32_t mbf = sbase + SM_MBF + lane * 8;
            const uint32_t mbe = sbase + SM_MBE + lane * 8;
            const uint32_t dst = sbase + SM_A + (uint32_t)lane * 32768u;
            int ep = 1;                 // fresh barrier: parity-1 wait passes
            #pragma unroll 1
            for (unsigned itg = (unsigned)lane; itg < 18u * T_; itg += RD) {
                const int t = (int)(itg / 18u);
                const int j = (int)(itg % 18u);
                const int p = j >> 1, hf = j & 1;
                mbar_wait_(mbe, (uint32_t)ep); ep ^= 1;
                const char* src0;
                size_t pls;
                if (p == 0) {
                    src0 = (const char*)g_xA + (size_t)t * 32768 + hf * 16384;
                    pls = (size_t)T_ * 32768;
                } else {
                    const int kc = (kc0 + p - 1) & 7;
                    flag_wait_(&g_flag[t][kc]);
                    src0 = (const char*)g_hA +
                           ((size_t)((t % 3) * 16) + kc) * 32768 + hf * 16384;
                    pls = (size_t)8 * 32768;
                }
                mbar_expect_tx_(mbf, 32768u);
                bulk_g2s_(dst, src0, 16384u, mbf);            // hi 128 rows
                bulk_g2s_(dst + 16384u, src0 + pls, 16384u, mbf);  // lo
            }
        }
    } else {
        // ====== compute warps: warp w owns rows w*16..+16 (half hf = w>>3) ====
        const int hf = w >> 3;
        const uint32_t akey = ((uint32_t)(lane & 7)) << 4;
        const uint32_t arow = (uint32_t)((w & 7) * 16 + (lane & 15)) * 128;
        uint32_t asw[4];
        #pragma unroll
        for (int ks = 0; ks < 4; ks++)
            asw[ks] = ((uint32_t)(ks * 32 + ((lane >> 4) * 16))) ^ akey;
        uint32_t bo;
        {
            uint32_t nrow = (uint32_t)(((lane >> 4) << 3) + (lane & 7));
            bo = nrow * BROW + ((uint32_t)((lane >> 3) & 1)) * 16;
        }

        float cst[2] = {0.f, 0.f};      // c-state: rows r, r+8 (one hcol/lane)

        int fp[RD] = {0, 0, 0, 0};
        const int L  = lane & 3;                 // local h-col
        const int u0 = (j0 & 63) + L;            // col within 64-col chunk

        #pragma unroll 1
        for (int t = 0; t < T_; t++) {
            float C[2][4];
            #pragma unroll
            for (int n = 0; n < 2; n++)
                #pragma unroll
                for (int q = 0; q < 4; q++) C[n][q] = 0.f;

            #pragma unroll 1
            for (int p = 0; p < 9; p++) {
                const unsigned itg = (unsigned)t * 18u + (unsigned)(2 * p + hf);
                const int s = (int)(itg & 3u);
                mbar_wait_(sbase + SM_MBF + s * 8, (uint32_t)fp[s]); fp[s] ^= 1;
                const uint32_t a0 = sbase + SM_A + (uint32_t)s * 32768u;
                const uint32_t koff =
                    (p == 0) ? 8u : (uint32_t)((kc0 + p - 1) & 7);
                const uint32_t bb = sbase + SM_B + koff * 128u;

                #pragma unroll
                for (int ks = 0; ks < 4; ks++) {
                    uint32_t Ah[4], Al[4], Bh[4], Bl[4];
                    LDM4(Ah, a0 + arow + asw[ks]);
                    LDM4(Al, a0 + 16384 + arow + asw[ks]);
                    LDM4(Bh, bb + bo + ks * 32);
                    LDM4(Bl, bb + BPLANE + bo + ks * 32);
                    MMA(C[0], Ah, Bh[0], Bh[1]);
                    MMA(C[1], Ah, Bh[2], Bh[3]);
                    MMA(C[0], Ah, Bl[0], Bl[1]);
                    MMA(C[1], Ah, Bl[2], Bl[3]);
                    MMA(C[0], Al, Bh[0], Bh[1]);
                    MMA(C[1], Al, Bh[2], Bh[3]);
                }
                if (lane == 0) mbar_arrive_(sbase + SM_MBE + s * 8);
            }

            // ---- epilogue: gates, write h to buf (t+1)%3, publish flag ----
            {
                const int nbuf = (t + 1) % 3;
                char* hb0 = (char*)g_hA +
                            (((size_t)nbuf * 2 + 0) * 8 + kc0) * 32768;
                char* hb1 = hb0 + 8 * 32768;
                #pragma unroll
                for (int rr = 0; rr < 2; rr++) {
                    const int r = w * 16 + (lane >> 2) + rr * 8;
                    const int c = rr * 2;
                    float iv = sigmoid_(C[0][c]     + bias_s[2 * L]);
                    float fv = sigmoid_(C[0][c + 1] + bias_s[2 * L + 1]);
                    float gv = tanh_   (C[1][c]     + bias_s[8 + 2 * L]);
                    float ov = sigmoid_(C[1][c + 1] + bias_s[8 + 2 * L + 1]);
                    cst[rr] = fv * cst[rr] + iv * gv;
                    float hval = ov * tanh_(cst[rr]);
                    __nv_bfloat16 hi = __float2bfloat16(hval);
                    __nv_bfloat16 lo =
                        __float2bfloat16(hval - __bfloat162float(hi));
                    uint32_t off = (uint32_t)r * 128 +
                                   (((uint32_t)u0 * 2) ^ (((uint32_t)r & 7) << 4));
                    *(__nv_bfloat16*)(hb0 + off) = hi;
                    *(__nv_bfloat16*)(hb1 + off) = lo;
                }
            }
            __threadfence();
            asm volatile("bar.sync 1, 512;" ::: "memory");  // compute warps only
            if (tid == 0) atomicAdd(&g_flag[t + 1][kc0], 1u);
        }

        // ---- final linear: h_last = input of step 512 -> buf 512%3 = 2 ----
        if (cta == 0) {
            if (tid == 0) {
                #pragma unroll
                for (int kc = 0; kc < 8; kc++) flag_wait_(&g_flag[T_][kc]);
            }
            asm volatile("bar.sync 1, 512;" ::: "memory");
            if (tid < B_) {
                const int b = tid;
                float s = 0.f;
                const char* hibase = (const char*)g_hA + (size_t)4 * 262144;
                const char* lobase = (const char*)g_hA + (size_t)5 * 262144;
                #pragma unroll 4
                for (int j = 0; j < H_; j++) {
                    uint32_t off =
                        (((uint32_t)(j >> 6)) * 256 + (uint32_t)b) * 128 +
                        (((uint32_t)(j & 63) * 2) ^ (((uint32_t)b & 7) << 4));
                    float hv =
                        __bfloat162float(*(const __nv_bfloat16*)(hibase + off)) +
                        __bfloat162float(*(const __nv_bfloat16*)(lobase + off));
                    s += hv * __ldg(&lin_w[j]);
                }
                out[b] = s + __ldg(&lin_b[0]);
            }
        }
    }

    __syncthreads();
    if (tid == 0) {
        #pragma unroll
        for (int s = 0; s < RD; s++) {
            mbar_inval_(sbase + SM_MBF + s * 8);
            mbar_inval_(sbase + SM_MBE + s * 8);
        }
    }
}

// ---------------- launch ----------------
extern "C" void kernel_launch(void* const* d_in, const int* in_sizes, int n_in,
                              void* d_out, int out_size)
{
    const float* x       = (const float*)d_in[0];
    const float* wih_mu  = (const float*)d_in[1];
    const float* wih_rho = (const float*)d_in[2];
    const float* wih_eps = (const float*)d_in[3];
    const float* whh_mu  = (const float*)d_in[4];
    const float* whh_rho = (const float*)d_in[5];
    const float* whh_eps = (const float*)d_in[6];
    const float* b_mu    = (const float*)d_in[7];
    const float* b_rho   = (const float*)d_in[8];
    const float* b_eps   = (const float*)d_in[9];
    const float* lin_w   = (const float*)d_in[10];
    const float* lin_b   = (const float*)d_in[11];
    float* out = (float*)d_out;

    static int inited = 0;
    if (!inited) {
        cudaFuncSetAttribute(lstm_hmma,
                             cudaFuncAttributeMaxDynamicSharedMemorySize, SMEM_BYTES);
        inited = 1;
    }

    bar_init_kernel<<<1, 256>>>();
    lstm_hmma<<<NCTA, NTHR, SMEM_BYTES>>>(x,
                                          wih_mu, wih_rho, wih_eps,
                                          whh_mu, whh_rho, whh_eps,
                                          b_mu, b_rho, b_eps,
                                          lin_w, lin_b, out);
}

// round 14
// speedup vs baseline: 1.1393x; 1.1393x over previous
#include <cuda_runtime.h>
#include <cuda_fp16.h>
#include <cstdint>

// ---------------- problem constants ----------------
#define B_ 256
#define T_ 512
#define D_ 64
#define H_ 512
#define G_ 2048
#define NCTA 128
#define NTHR 544          // 16 compute warps + 1 producer warp
#define NCW 16
#define HC 4              // h-columns per CTA (16 gate cols)
#define NCOL 16           // gate cols per CTA
#define FLAGTGT 16u       // CTAs producing each 64-col chunk
#define BROW 1168         // padded B row bytes (9*128 + 16)
#define BPLANE (NCOL * BROW)

// ---------------- dynamic SMEM layout (bytes) ----------------
#define SM_MBF 0                         // 2 full barriers
#define SM_MBE 64                        // 2 empty barriers
#define SM_BIAS 128
#define SM_A 1024                        // ring: 2 x 65536 (hi 32K + lo 32K)
#define SM_B (SM_A + 131072)             // 2 planes x BPLANE
#define SMEM_BYTES (SM_B + 2 * BPLANE)   // 169472

// ---------------- persistent device state ----------------
// h fp16 K-blocked swizzled, TRIPLE buffered: [buf][plane][kc][row 256][64]
__device__ __align__(128) __half g_hA[3][2][8][256][64];
// x fp16 per-step K-blocked swizzled: [plane][t][row 256][64]
__device__ __align__(128) __half g_xA[2][T_][256][64];
__device__ unsigned g_flag[T_ + 1][8];   // readiness of input chunk kc at step t
__device__ unsigned g_count, g_gen;

// ---------------- math helpers ----------------
__device__ __forceinline__ float softplus_(float r) {
    return (r > 15.f) ? r : log1pf(expf(r));
}
__device__ __forceinline__ float sample_(float mu, float rho, float eps) {
    return mu + softplus_(rho) * eps;
}
__device__ __forceinline__ float sigmoid_(float x) {
    return __fdividef(1.f, 1.f + __expf(-x));
}
__device__ __forceinline__ float tanh_(float x) {
    return __fdividef(2.f, 1.f + __expf(-2.f * x)) - 1.f;
}

// ---------------- PTX helpers ----------------
__device__ __forceinline__ uint32_t smem_u32_(const void* p) {
    uint32_t a;
    asm("{ .reg .u64 t; cvta.to.shared.u64 t, %1; cvt.u32.u64 %0, t; }"
        : "=r"(a) : "l"(p));
    return a;
}
__device__ __forceinline__ void mbar_init_(uint32_t a, uint32_t cnt) {
    asm volatile("mbarrier.init.shared.b64 [%0], %1;" :: "r"(a), "r"(cnt) : "memory");
}
__device__ __forceinline__ void mbar_inval_(uint32_t a) {
    asm volatile("mbarrier.inval.shared.b64 [%0];" :: "r"(a) : "memory");
}
__device__ __forceinline__ void mbar_expect_tx_(uint32_t a, uint32_t bytes) {
    asm volatile("mbarrier.arrive.expect_tx.shared.b64 _, [%0], %1;"
                 :: "r"(a), "r"(bytes) : "memory");
}
__device__ __forceinline__ void mbar_arrive_(uint32_t a) {
    asm volatile("mbarrier.arrive.shared.b64 _, [%0];" :: "r"(a) : "memory");
}
__device__ __forceinline__ void mbar_wait_(uint32_t a, uint32_t parity) {
    uint32_t done;
    asm volatile(
        "{\n\t.reg .pred p;\n\t"
        "mbarrier.try_wait.parity.acquire.cta.shared::cta.b64 p, [%1], %2;\n\t"
        "selp.b32 %0, 1, 0, p;\n\t}"
        : "=r"(done) : "r"(a), "r"(parity) : "memory");
    if (!done) {
        asm volatile(
            "{\n\t.reg .pred P1;\n\t"
            "W_%=:\n\t"
            "mbarrier.try_wait.parity.acquire.cta.shared::cta.b64 P1, [%0], %1, 0x989680;\n\t"
            "@P1 bra.uni D_%=;\n\t"
            "bra.uni W_%=;\n\t"
            "D_%=:\n\t}"
            :: "r"(a), "r"(parity) : "memory");
    }
}
__device__ __forceinline__ void bulk_g2s_(uint32_t dst, const void* src,
                                          uint32_t bytes, uint32_t mbar) {
    asm volatile(
        "cp.async.bulk.shared::cluster.global.mbarrier::complete_tx::bytes "
        "[%0], [%1], %2, [%3];"
        :: "r"(dst), "l"(src), "r"(bytes), "r"(mbar) : "memory");
}
__device__ __forceinline__ void flag_wait_(const unsigned* p) {
    unsigned v;
    do {
        asm volatile("ld.global.cg.u32 %0, [%1];" : "=r"(v) : "l"(p));
        if (v >= FLAGTGT) break;
        __nanosleep(16);
    } while (1);
    __threadfence();
}

#define LDM4(R, A) \
    asm volatile("ldmatrix.sync.aligned.m8n8.x4.shared.b16 {%0,%1,%2,%3}, [%4];" \
        : "=r"((R)[0]), "=r"((R)[1]), "=r"((R)[2]), "=r"((R)[3]) : "r"(A))

#define MMA(Cf, Af, Bf0, Bf1) \
    asm volatile("mma.sync.aligned.m16n8k16.row.col.f32.f16.f16.f32 " \
        "{%0,%1,%2,%3}, {%4,%5,%6,%7}, {%8,%9}, {%0,%1,%2,%3};" \
        : "+f"((Cf)[0]), "+f"((Cf)[1]), "+f"((Cf)[2]), "+f"((Cf)[3]) \
        : "r"((Af)[0]), "r"((Af)[1]), "r"((Af)[2]), "r"((Af)[3]), \
          "r"(Bf0), "r"(Bf1))

extern "C" __global__ void bar_init_kernel() {
    const int tid = threadIdx.x;
    unsigned* f = (unsigned*)g_flag;
    for (int i = tid; i < (T_ + 1) * 8; i += blockDim.x)
        f[i] = (i < 8) ? FLAGTGT : 0u;     // step-0 input (zeros) pre-ready
    if (tid == 0) { g_count = 0; g_gen = 0; }
}

// ---------------- one-shot grid barrier (startup only) ----------------
__device__ __forceinline__ void grid_sync_(unsigned target) {
    __syncthreads();
    if (threadIdx.x == 0) {
        __threadfence();
        unsigned a = atomicAdd(&g_count, 1u);
        if (a == NCTA - 1) {
            g_count = 0;
            __threadfence();
            atomicExch(&g_gen, target);
        } else {
            unsigned g;
            do {
                asm volatile("ld.global.cg.u32 %0, [%1];" : "=r"(g) : "l"(&g_gen));
                if (g >= target) break;
                __nanosleep(32);
            } while (1);
        }
        __threadfence();
    }
    __syncthreads();
}

// gate/hcol mapping within the 16 local cols (4 gates x 4 h-cols, no shuffles)
__device__ __forceinline__ int colmap_(int n, int j0) {
    int gate = ((n >> 3) << 1) | (n & 1);
    int hcol = (n >> 1) & 3;
    return gate * H_ + j0 + hcol;
}

// ---------------- main persistent kernel ----------------
extern "C" __global__ void __launch_bounds__(NTHR, 1)
lstm_hmma(const float* __restrict__ x,
          const float* __restrict__ wih_mu, const float* __restrict__ wih_rho,
          const float* __restrict__ wih_eps,
          const float* __restrict__ whh_mu, const float* __restrict__ whh_rho,
          const float* __restrict__ whh_eps,
          const float* __restrict__ b_mu,   const float* __restrict__ b_rho,
          const float* __restrict__ b_eps,
          const float* __restrict__ lin_w,  const float* __restrict__ lin_b,
          float* __restrict__ out)
{
    extern __shared__ char smem[];
    const uint32_t sbase = smem_u32_(smem);
    const uint32_t mb_f[2] = { sbase + SM_MBF, sbase + SM_MBF + 8 };
    const uint32_t mb_e[2] = { sbase + SM_MBE, sbase + SM_MBE + 8 };
    float* bias_s = (float*)(smem + SM_BIAS);

    const int tid  = threadIdx.x;
    const int lane = tid & 31;
    const int w    = tid >> 5;          // 0..15 compute, 16 producer
    const int cta  = blockIdx.x;
    const int j0   = cta * HC;          // first h-col
    const int kc0  = j0 >> 6;           // h chunk our cols land in

    if (tid == 0) {
        mbar_init_(mb_f[0], 1); mbar_init_(mb_f[1], 1);
        mbar_init_(mb_e[0], NCW); mbar_init_(mb_e[1], NCW);
    }

    // ---- sample W into SMEM B planes (fp16; lo plane written, unused) ----
    for (int idx = tid; idx < NCOL * 576; idx += NTHR) {
        int n = idx / 576, k = idx - n * 576;
        int col = colmap_(n, j0);
        float wv;
        if (k < 512) {
            int gi = k * G_ + col;
            wv = sample_(whh_mu[gi], whh_rho[gi], whh_eps[gi]);
        } else {
            int gi = (k - 512) * G_ + col;
            wv = sample_(wih_mu[gi], wih_rho[gi], wih_eps[gi]);
        }
        __half hi = __float2half(wv);
        __half lo = __float2half(wv - __half2float(hi));
        *(__half*)(smem + SM_B + 0 * BPLANE + n * BROW + k * 2) = hi;
        *(__half*)(smem + SM_B + 1 * BPLANE + n * BROW + k * 2) = lo;
    }
    if (tid < NCOL) {
        int col = colmap_(tid, j0);
        bias_s[tid] = sample_(b_mu[col], b_rho[col], b_eps[col]);
    }

    // ---- build swizzled fp16 x hi/lo planes + zero h buf0 (grid-wide) ----
    {
        const int gtid = cta * NTHR + tid;
        const int gn = NCTA * NTHR;
        for (int i = gtid; i < B_ * T_ * D_; i += gn) {
            int d = i & 63, r = i >> 6;
            int t = r & 511, b = r >> 9;            // x is [b][t][d]
            float v = __ldg(&x[i]);
            __half hi = __float2half(v);
            __half lo = __float2half(v - __half2float(hi));
            uint32_t off = ((uint32_t)t * 256 + (uint32_t)b) * 128 +
                           (((uint32_t)d * 2) ^ (((uint32_t)b & 7) << 4));
            *(__half*)((char*)g_xA + off) = hi;
            *(__half*)((char*)g_xA + (size_t)T_ * 32768 + off) = lo;
        }
        uint32_t* hz = (uint32_t*)g_hA;             // buf0, both planes
        for (int i = gtid; i < 131072; i += gn) hz[i] = 0u;
    }

    grid_sync_(1);

    // ================= producer warp: lane s owns ring slot s =================
    if (w == NCW) {
        if (lane < 2) {
            int ep = 1;                 // fresh barrier: parity-1 wait passes
            #pragma unroll 1
            for (unsigned itg = (unsigned)lane; itg < 9u * T_; itg += 2) {
                const int t = (int)(itg / 9u);
                const int item = (int)(itg % 9u);
                mbar_wait_(mb_e[lane], (uint32_t)ep); ep ^= 1;
                const char* src0;
                size_t pls;
                if (item == 0) {
                    src0 = (const char*)g_xA + (size_t)t * 32768;
                    pls = (size_t)T_ * 32768;
                } else {
                    const int kc = item - 1;
                    flag_wait_(&g_flag[t][kc]);
                    src0 = (const char*)g_hA +
                           ((size_t)((t % 3) * 2) * 8 + kc) * 32768;
                    pls = (size_t)8 * 32768;
                }
                mbar_expect_tx_(mb_f[lane], 65536u);
                const uint32_t dst = sbase + SM_A + (uint32_t)lane * 65536u;
                bulk_g2s_(dst, src0, 32768u, mb_f[lane]);
                bulk_g2s_(dst + 32768u, src0 + pls, 32768u, mb_f[lane]);
            }
        }
    } else {
        // ====== compute warps: warp w owns rows w*16..+16, all 16 cols ========
        const uint32_t akey = ((uint32_t)(lane & 7)) << 4;
        const uint32_t arow = (uint32_t)(w * 16 + (lane & 15)) * 128;
        uint32_t asw[4];
        #pragma unroll
        for (int ks = 0; ks < 4; ks++)
            asw[ks] = ((uint32_t)(ks * 32 + ((lane >> 4) * 16))) ^ akey;
        uint32_t bo;
        {
            uint32_t nrow = (uint32_t)(((lane >> 4) << 3) + (lane & 7));
            bo = nrow * BROW + ((uint32_t)((lane >> 3) & 1)) * 16;
        }

        float cst[2] = {0.f, 0.f};      // c-state: rows r, r+8 (one hcol/lane)

        int fp[2] = {0, 0};
        unsigned itg = 0;
        const int L  = lane & 3;                 // local h-col
        const int u0 = (j0 & 63) + L;            // col within 64-col chunk

        #pragma unroll 1
        for (int t = 0; t < T_; t++) {
            float C[2][4];
            #pragma unroll
            for (int n = 0; n < 2; n++)
                #pragma unroll
                for (int q = 0; q < 4; q++) C[n][q] = 0.f;

            #pragma unroll 1
            for (int item = 0; item < 9; item++) {
                const int s = (int)(itg & 1u); itg++;
                mbar_wait_(mb_f[s], (uint32_t)fp[s]); fp[s] ^= 1;
                const uint32_t a0 = sbase + SM_A + (uint32_t)s * 65536u;
                const uint32_t koff = (item == 0) ? 8u : (uint32_t)(item - 1);
                const uint32_t bb = sbase + SM_B + koff * 128u;

                #pragma unroll
                for (int ks = 0; ks < 4; ks++) {
                    uint32_t Ah[4], Al[4], Bh[4];
                    LDM4(Ah, a0 + arow + asw[ks]);
                    LDM4(Al, a0 + 32768 + arow + asw[ks]);
                    LDM4(Bh, bb + bo + ks * 32);
                    MMA(C[0], Ah, Bh[0], Bh[1]);
                    MMA(C[1], Ah, Bh[2], Bh[3]);
                    MMA(C[0], Al, Bh[0], Bh[1]);
                    MMA(C[1], Al, Bh[2], Bh[3]);
                }
                if (lane == 0) mbar_arrive_(mb_e[s]);
            }

            // ---- epilogue: gates, write fp16 hi/lo h to buf (t+1)%3 ----
            {
                const int nbuf = (t + 1) % 3;
                char* hb0 = (char*)g_hA +
                            (((size_t)nbuf * 2 + 0) * 8 + kc0) * 32768;
                char* hb1 = hb0 + 8 * 32768;
                #pragma unroll
                for (int rr = 0; rr < 2; rr++) {
                    const int r = w * 16 + (lane >> 2) + rr * 8;
                    const int c = rr * 2;
                    float iv = sigmoid_(C[0][c]     + bias_s[2 * L]);
                    float fv = sigmoid_(C[0][c + 1] + bias_s[2 * L + 1]);
                    float gv = tanh_   (C[1][c]     + bias_s[8 + 2 * L]);
                    float ov = sigmoid_(C[1][c + 1] + bias_s[8 + 2 * L + 1]);
                    cst[rr] = fv * cst[rr] + iv * gv;
                    float hval = ov * tanh_(cst[rr]);
                    __half hi = __float2half(hval);
                    __half lo = __float2half(hval - __half2float(hi));
                    uint32_t off = (uint32_t)r * 128 +
                                   (((uint32_t)u0 * 2) ^ (((uint32_t)r & 7) << 4));
                    *(__half*)(hb0 + off) = hi;
                    *(__half*)(hb1 + off) = lo;
                }
            }
            __threadfence();
            asm volatile("bar.sync 1, 512;" ::: "memory");  // compute warps only
            if (tid == 0) atomicAdd(&g_flag[t + 1][kc0], 1u);
        }

        // ---- final linear: h_last = input of step 512 -> buf 512%3 = 2 ----
        if (cta == 0) {
            if (tid == 0) {
                #pragma unroll
                for (int kc = 0; kc < 8; kc++) flag_wait_(&g_flag[T_][kc]);
            }
            asm volatile("bar.sync 1, 512;" ::: "memory");
            if (tid < B_) {
                const int b = tid;
                float s = 0.f;
                const char* hibase = (const char*)g_hA + (size_t)4 * 262144;
                const char* lobase = (const char*)g_hA + (size_t)5 * 262144;
                #pragma unroll 4
                for (int j = 0; j < H_; j++) {
                    uint32_t off =
                        (((uint32_t)(j >> 6)) * 256 + (uint32_t)b) * 128 +
                        (((uint32_t)(j & 63) * 2) ^ (((uint32_t)b & 7) << 4));
                    float hv =
                        __half2float(*(const __half*)(hibase + off)) +
                        __half2float(*(const __half*)(lobase + off));
                    s += hv * __ldg(&lin_w[j]);
                }
                out[b] = s + __ldg(&lin_b[0]);
            }
        }
    }

    __syncthreads();
    if (tid == 0) {
        mbar_inval_(mb_f[0]); mbar_inval_(mb_f[1]);
        mbar_inval_(mb_e[0]); mbar_inval_(mb_e[1]);
    }
}

// ---------------- launch ----------------
extern "C" void kernel_launch(void* const* d_in, const int* in_sizes, int n_in,
                              void* d_out, int out_size)
{
    const float* x       = (const float*)d_in[0];
    const float* wih_mu  = (const float*)d_in[1];
    const float* wih_rho = (const float*)d_in[2];
    const float* wih_eps = (const float*)d_in[3];
    const float* whh_mu  = (const float*)d_in[4];
    const float* whh_rho = (const float*)d_in[5];
    const float* whh_eps = (const float*)d_in[6];
    const float* b_mu    = (const float*)d_in[7];
    const float* b_rho   = (const float*)d_in[8];
    const float* b_eps   = (const float*)d_in[9];
    const float* lin_w   = (const float*)d_in[10];
    const float* lin_b   = (const float*)d_in[11];
    float* out = (float*)d_out;

    static int inited = 0;
    if (!inited) {
        cudaFuncSetAttribute(lstm_hmma,
                             cudaFuncAttributeMaxDynamicSharedMemorySize, SMEM_BYTES);
        inited = 1;
    }

    bar_init_kernel<<<1, 256>>>();
    lstm_hmma<<<NCTA, NTHR, SMEM_BYTES>>>(x,
                                          wih_mu, wih_rho, wih_eps,
                                          whh_mu, whh_rho, whh_eps,
                                          b_mu, b_rho, b_eps,
                                          lin_w, lin_b, out);
}

// round 15
// speedup vs baseline: 1.2270x; 1.0770x over previous
#include <cuda_runtime.h>
#include <cuda_fp16.h>
#include <cstdint>

// ---------------- problem constants ----------------
#define B_ 256
#define T_ 512
#define D_ 64
#define H_ 512
#define G_ 2048
#define NCTA 128
#define NTHR 544          // 16 compute warps + 1 producer warp
#define NCW 16
#define HC 4              // h-columns per CTA (16 gate cols)
#define NCOL 16           // gate cols per CTA
#define FLAGTGT 16u       // CTAs producing each 64-col chunk
#define BROW 1168         // padded B row bytes (9*128 + 16)
#define BPLANE (NCOL * BROW)

// ---------------- dynamic SMEM layout (bytes) ----------------
#define SM_MBF 0                         // 2 full barriers
#define SM_MBE 64                        // 2 empty barriers
#define SM_BIAS 128
#define SM_A 1024                        // ring: 2 x 32768 (single A plane)
#define SM_B (SM_A + 65536)              // 2 planes x BPLANE
#define SMEM_BYTES (SM_B + 2 * BPLANE)   // 103936

// ---------------- persistent device state ----------------
// h fp16 single-plane, K-blocked swizzled, TRIPLE buffered: [buf][kc][row][64]
__device__ __align__(128) __half g_hA[3][8][256][64];
// x fp16 single-plane per-step K-blocked swizzled: [t][row][64]
__device__ __align__(128) __half g_xA[T_][256][64];
__device__ unsigned g_flag[T_ + 1][8];   // readiness of input chunk kc at step t
__device__ unsigned g_count, g_gen;

// ---------------- math helpers ----------------
__device__ __forceinline__ float softplus_(float r) {
    return (r > 15.f) ? r : log1pf(expf(r));
}
__device__ __forceinline__ float sample_(float mu, float rho, float eps) {
    return mu + softplus_(rho) * eps;
}
__device__ __forceinline__ float sigmoid_(float x) {
    return __fdividef(1.f, 1.f + __expf(-x));
}
__device__ __forceinline__ float tanh_(float x) {
    return __fdividef(2.f, 1.f + __expf(-2.f * x)) - 1.f;
}

// ---------------- PTX helpers ----------------
__device__ __forceinline__ uint32_t smem_u32_(const void* p) {
    uint32_t a;
    asm("{ .reg .u64 t; cvta.to.shared.u64 t, %1; cvt.u32.u64 %0, t; }"
        : "=r"(a) : "l"(p));
    return a;
}
__device__ __forceinline__ void mbar_init_(uint32_t a, uint32_t cnt) {
    asm volatile("mbarrier.init.shared.b64 [%0], %1;" :: "r"(a), "r"(cnt) : "memory");
}
__device__ __forceinline__ void mbar_inval_(uint32_t a) {
    asm volatile("mbarrier.inval.shared.b64 [%0];" :: "r"(a) : "memory");
}
__device__ __forceinline__ void mbar_expect_tx_(uint32_t a, uint32_t bytes) {
    asm volatile("mbarrier.arrive.expect_tx.shared.b64 _, [%0], %1;"
                 :: "r"(a), "r"(bytes) : "memory");
}
__device__ __forceinline__ void mbar_arrive_(uint32_t a) {
    asm volatile("mbarrier.arrive.shared.b64 _, [%0];" :: "r"(a) : "memory");
}
__device__ __forceinline__ void mbar_wait_(uint32_t a, uint32_t parity) {
    uint32_t done;
    asm volatile(
        "{\n\t.reg .pred p;\n\t"
        "mbarrier.try_wait.parity.acquire.cta.shared::cta.b64 p, [%1], %2;\n\t"
        "selp.b32 %0, 1, 0, p;\n\t}"
        : "=r"(done) : "r"(a), "r"(parity) : "memory");
    if (!done) {
        asm volatile(
            "{\n\t.reg .pred P1;\n\t"
            "W_%=:\n\t"
            "mbarrier.try_wait.parity.acquire.cta.shared::cta.b64 P1, [%0], %1, 0x989680;\n\t"
            "@P1 bra.uni D_%=;\n\t"
            "bra.uni W_%=;\n\t"
            "D_%=:\n\t}"
            :: "r"(a), "r"(parity) : "memory");
    }
}
__device__ __forceinline__ void bulk_g2s_(uint32_t dst, const void* src,
                                          uint32_t bytes, uint32_t mbar) {
    asm volatile(
        "cp.async.bulk.shared::cluster.global.mbarrier::complete_tx::bytes "
        "[%0], [%1], %2, [%3];"
        :: "r"(dst), "l"(src), "r"(bytes), "r"(mbar) : "memory");
}
// IMPORTANT: the __nanosleep in this spin is load-bearing for correctness
// (R11/R13 removed it and silently corrupted; R8/R12/R14 kept it and passed).
__device__ __forceinline__ void flag_wait_(const unsigned* p) {
    unsigned v;
    do {
        asm volatile("ld.global.cg.u32 %0, [%1];" : "=r"(v) : "l"(p));
        if (v >= FLAGTGT) break;
        __nanosleep(16);
    } while (1);
    __threadfence();
}

#define LDM4(R, A) \
    asm volatile("ldmatrix.sync.aligned.m8n8.x4.shared.b16 {%0,%1,%2,%3}, [%4];" \
        : "=r"((R)[0]), "=r"((R)[1]), "=r"((R)[2]), "=r"((R)[3]) : "r"(A))

#define MMA(Cf, Af, Bf0, Bf1) \
    asm volatile("mma.sync.aligned.m16n8k16.row.col.f32.f16.f16.f32 " \
        "{%0,%1,%2,%3}, {%4,%5,%6,%7}, {%8,%9}, {%0,%1,%2,%3};" \
        : "+f"((Cf)[0]), "+f"((Cf)[1]), "+f"((Cf)[2]), "+f"((Cf)[3]) \
        : "r"((Af)[0]), "r"((Af)[1]), "r"((Af)[2]), "r"((Af)[3]), \
          "r"(Bf0), "r"(Bf1))

extern "C" __global__ void bar_init_kernel() {
    const int tid = threadIdx.x;
    unsigned* f = (unsigned*)g_flag;
    for (int i = tid; i < (T_ + 1) * 8; i += blockDim.x)
        f[i] = (i < 8) ? FLAGTGT : 0u;     // step-0 input (zeros) pre-ready
    if (tid == 0) { g_count = 0; g_gen = 0; }
}

// ---------------- one-shot grid barrier (startup only) ----------------
__device__ __forceinline__ void grid_sync_(unsigned target) {
    __syncthreads();
    if (threadIdx.x == 0) {
        __threadfence();
        unsigned a = atomicAdd(&g_count, 1u);
        if (a == NCTA - 1) {
            g_count = 0;
            __threadfence();
            atomicExch(&g_gen, target);
        } else {
            unsigned g;
            do {
                asm volatile("ld.global.cg.u32 %0, [%1];" : "=r"(g) : "l"(&g_gen));
                if (g >= target) break;
                __nanosleep(32);
            } while (1);
        }
        __threadfence();
    }
    __syncthreads();
}

// gate/hcol mapping within the 16 local cols (4 gates x 4 h-cols, no shuffles)
__device__ __forceinline__ int colmap_(int n, int j0) {
    int gate = ((n >> 3) << 1) | (n & 1);
    int hcol = (n >> 1) & 3;
    return gate * H_ + j0 + hcol;
}

// ---------------- main persistent kernel ----------------
extern "C" __global__ void __launch_bounds__(NTHR, 1)
lstm_hmma(const float* __restrict__ x,
          const float* __restrict__ wih_mu, const float* __restrict__ wih_rho,
          const float* __restrict__ wih_eps,
          const float* __restrict__ whh_mu, const float* __restrict__ whh_rho,
          const float* __restrict__ whh_eps,
          const float* __restrict__ b_mu,   const float* __restrict__ b_rho,
          const float* __restrict__ b_eps,
          const float* __restrict__ lin_w,  const float* __restrict__ lin_b,
          float* __restrict__ out)
{
    extern __shared__ char smem[];
    const uint32_t sbase = smem_u32_(smem);
    const uint32_t mb_f[2] = { sbase + SM_MBF, sbase + SM_MBF + 8 };
    const uint32_t mb_e[2] = { sbase + SM_MBE, sbase + SM_MBE + 8 };
    float* bias_s = (float*)(smem + SM_BIAS);

    const int tid  = threadIdx.x;
    const int lane = tid & 31;
    const int w    = tid >> 5;          // 0..15 compute, 16 producer
    const int cta  = blockIdx.x;
    const int j0   = cta * HC;          // first h-col
    const int kc0  = j0 >> 6;           // h chunk our cols land in

    if (tid == 0) {
        mbar_init_(mb_f[0], 1); mbar_init_(mb_f[1], 1);
        mbar_init_(mb_e[0], NCW); mbar_init_(mb_e[1], NCW);
    }

    // ---- sample W into SMEM B planes (fp16 hi + lo, both used) ----
    for (int idx = tid; idx < NCOL * 576; idx += NTHR) {
        int n = idx / 576, k = idx - n * 576;
        int col = colmap_(n, j0);
        float wv;
        if (k < 512) {
            int gi = k * G_ + col;
            wv = sample_(whh_mu[gi], whh_rho[gi], whh_eps[gi]);
        } else {
            int gi = (k - 512) * G_ + col;
            wv = sample_(wih_mu[gi], wih_rho[gi], wih_eps[gi]);
        }
        __half hi = __float2half(wv);
        __half lo = __float2half(wv - __half2float(hi));
        *(__half*)(smem + SM_B + 0 * BPLANE + n * BROW + k * 2) = hi;
        *(__half*)(smem + SM_B + 1 * BPLANE + n * BROW + k * 2) = lo;
    }
    if (tid < NCOL) {
        int col = colmap_(tid, j0);
        bias_s[tid] = sample_(b_mu[col], b_rho[col], b_eps[col]);
    }

    // ---- build swizzled fp16 x plane + zero h buf0 (grid-wide striped) ----
    {
        const int gtid = cta * NTHR + tid;
        const int gn = NCTA * NTHR;
        for (int i = gtid; i < B_ * T_ * D_; i += gn) {
            int d = i & 63, r = i >> 6;
            int t = r & 511, b = r >> 9;            // x is [b][t][d]
            float v = __ldg(&x[i]);
            uint32_t off = ((uint32_t)t * 256 + (uint32_t)b) * 128 +
                           (((uint32_t)d * 2) ^ (((uint32_t)b & 7) << 4));
            *(__half*)((char*)g_xA + off) = __float2half(v);
        }
        uint32_t* hz = (uint32_t*)g_hA;             // buf0: 262144 B
        for (int i = gtid; i < 65536; i += gn) hz[i] = 0u;
    }

    grid_sync_(1);

    // ================= producer warp: lane s owns ring slot s =================
    // 9 items/step: item 0 = x chunk (no flag), items 1..8 = h chunk kc=item-1.
    if (w == NCW) {
        if (lane < 2) {
            int ep = 1;                 // fresh barrier: parity-1 wait passes
            #pragma unroll 1
            for (unsigned itg = (unsigned)lane; itg < 9u * T_; itg += 2) {
                const int t = (int)(itg / 9u);
                const int item = (int)(itg % 9u);
                mbar_wait_(mb_e[lane], (uint32_t)ep); ep ^= 1;
                const char* src;
                if (item == 0) {
                    src = (const char*)g_xA + (size_t)t * 32768;
                } else {
                    const int kc = item - 1;
                    flag_wait_(&g_flag[t][kc]);
                    src = (const char*)g_hA + ((size_t)(t % 3) * 8 + kc) * 32768;
                }
                mbar_expect_tx_(mb_f[lane], 32768u);
                const uint32_t dst = sbase + SM_A + (uint32_t)lane * 32768u;
                bulk_g2s_(dst, src, 32768u, mb_f[lane]);
            }
        }
    } else {
        // ====== compute warps: warp w owns rows w*16..+16, all 16 cols ========
        const uint32_t akey = ((uint32_t)(lane & 7)) << 4;
        const uint32_t arow = (uint32_t)(w * 16 + (lane & 15)) * 128;
        uint32_t asw[4];
        #pragma unroll
        for (int ks = 0; ks < 4; ks++)
            asw[ks] = ((uint32_t)(ks * 32 + ((lane >> 4) * 16))) ^ akey;
        uint32_t bo;
        {
            uint32_t nrow = (uint32_t)(((lane >> 4) << 3) + (lane & 7));
            bo = nrow * BROW + ((uint32_t)((lane >> 3) & 1)) * 16;
        }

        float cst[2] = {0.f, 0.f};      // c-state: rows r, r+8 (one hcol/lane)

        int fp[2] = {0, 0};
        unsigned itg = 0;
        const int L  = lane & 3;                 // local h-col
        const int u0 = (j0 & 63) + L;            // col within 64-col chunk

        #pragma unroll 1
        for (int t = 0; t < T_; t++) {
            float C[2][4];
            #pragma unroll
            for (int n = 0; n < 2; n++)
                #pragma unroll
                for (int q = 0; q < 4; q++) C[n][q] = 0.f;

            #pragma unroll 1
            for (int item = 0; item < 9; item++) {
                const int s = (int)(itg & 1u); itg++;
                mbar_wait_(mb_f[s], (uint32_t)fp[s]); fp[s] ^= 1;
                const uint32_t a0 = sbase + SM_A + (uint32_t)s * 32768u;
                const uint32_t koff = (item == 0) ? 8u : (uint32_t)(item - 1);
                const uint32_t bb = sbase + SM_B + koff * 128u;

                #pragma unroll
                for (int ks = 0; ks < 4; ks++) {
                    uint32_t Ah[4], Bh[4], Bl[4];
                    LDM4(Ah, a0 + arow + asw[ks]);
                    LDM4(Bh, bb + bo + ks * 32);
                    LDM4(Bl, bb + BPLANE + bo + ks * 32);
                    MMA(C[0], Ah, Bh[0], Bh[1]);
                    MMA(C[1], Ah, Bh[2], Bh[3]);
                    MMA(C[0], Ah, Bl[0], Bl[1]);
                    MMA(C[1], Ah, Bl[2], Bl[3]);
                }
                if (lane == 0) mbar_arrive_(mb_e[s]);
            }

            // ---- epilogue: gates, write fp16 h to buf (t+1)%3, publish flag ----
            {
                const int nbuf = (t + 1) % 3;
                char* hb = (char*)g_hA + ((size_t)nbuf * 8 + kc0) * 32768;
                #pragma unroll
                for (int rr = 0; rr < 2; rr++) {
                    const int r = w * 16 + (lane >> 2) + rr * 8;
                    const int c = rr * 2;
                    float iv = sigmoid_(C[0][c]     + bias_s[2 * L]);
                    float fv = sigmoid_(C[0][c + 1] + bias_s[2 * L + 1]);
                    float gv = tanh_   (C[1][c]     + bias_s[8 + 2 * L]);
                    float ov = sigmoid_(C[1][c + 1] + bias_s[8 + 2 * L + 1]);
                    cst[rr] = fv * cst[rr] + iv * gv;
                    float hval = ov * tanh_(cst[rr]);
                    uint32_t off = (uint32_t)r * 128 +
                                   (((uint32_t)u0 * 2) ^ (((uint32_t)r & 7) << 4));
                    *(__half*)(hb + off) = __float2half(hval);
                }
            }
            __threadfence();
            asm volatile("bar.sync 1, 512;" ::: "memory");  // compute warps only
            if (tid == 0) atomicAdd(&g_flag[t + 1][kc0], 1u);
        }

        // ---- final linear: h_last = input of step 512 -> buf 512%3 = 2 ----
        if (cta == 0) {
            if (tid == 0) {
                #pragma unroll
                for (int kc = 0; kc < 8; kc++) flag_wait_(&g_flag[T_][kc]);
            }
            asm volatile("bar.sync 1, 512;" ::: "memory");
            if (tid < B_) {
                const int b = tid;
                float s = 0.f;
                const char* hbase = (const char*)g_hA + (size_t)2 * 262144;
                #pragma unroll 4
                for (int j = 0; j < H_; j++) {
                    uint32_t off =
                        (((uint32_t)(j >> 6)) * 256 + (uint32_t)b) * 128 +
                        (((uint32_t)(j & 63) * 2) ^ (((uint32_t)b & 7) << 4));
                    float hv = __half2float(*(const __half*)(hbase + off));
                    s += hv * __ldg(&lin_w[j]);
                }
                out[b] = s + __ldg(&lin_b[0]);
            }
        }
    }

    __syncthreads();
    if (tid == 0) {
        mbar_inval_(mb_f[0]); mbar_inval_(mb_f[1]);
        mbar_inval_(mb_e[0]); mbar_inval_(mb_e[1]);
    }
}

// ---------------- launch ----------------
extern "C" void kernel_launch(void* const* d_in, const int* in_sizes, int n_in,
                              void* d_out, int out_size)
{
    const float* x       = (const float*)d_in[0];
    const float* wih_mu  = (const float*)d_in[1];
    const float* wih_rho = (const float*)d_in[2];
    const float* wih_eps = (const float*)d_in[3];
    const float* whh_mu  = (const float*)d_in[4];
    const float* whh_rho = (const float*)d_in[5];
    const float* whh_eps = (const float*)d_in[6];
    const float* b_mu    = (const float*)d_in[7];
    const float* b_rho   = (const float*)d_in[8];
    const float* b_eps   = (const float*)d_in[9];
    const float* lin_w   = (const float*)d_in[10];
    const float* lin_b   = (const float*)d_in[11];
    float* out = (float*)d_out;

    static int inited = 0;
    if (!inited) {
        cudaFuncSetAttribute(lstm_hmma,
                             cudaFuncAttributeMaxDynamicSharedMemorySize, SMEM_BYTES);
        inited = 1;
    }

    bar_init_kernel<<<1, 256>>>();
    lstm_hmma<<<NCTA, NTHR, SMEM_BYTES>>>(x,
                                          wih_mu, wih_rho, wih_eps,
                                          whh_mu, whh_rho, whh_eps,
                                          b_mu, b_rho, b_eps,
                                          lin_w, lin_b, out);
}

// round 16
// speedup vs baseline: 1.4493x; 1.1812x over previous
#include <cuda_runtime.h>
#include <cuda_fp16.h>
#include <cstdint>

// ---------------- problem constants ----------------
#define B_ 256
#define T_ 512
#define D_ 64
#define H_ 512
#define G_ 2048
#define NCTA 128
#define NTHR 544          // 16 compute warps + 1 producer warp
#define NCW 16
#define HC 4              // h-columns per CTA (16 gate cols)
#define NCOL 16           // gate cols per CTA
#define FLAGTGT 16u       // CTAs producing each 64-col chunk
#define RD 4              // ring depth (32KB single-plane items)
#define BROW 1168         // padded B row bytes (9*128 + 16)
#define BPLANE (NCOL * BROW)

// ---------------- dynamic SMEM layout (bytes) ----------------
#define SM_MBF 0                         // RD full barriers
#define SM_MBE 64                        // RD empty barriers
#define SM_BIAS 128
#define SM_A 1024                        // ring: 4 x 32768
#define SM_B (SM_A + RD * 32768)         // 2 planes x BPLANE
#define SMEM_BYTES (SM_B + 2 * BPLANE)   // 169472

// ---------------- persistent device state ----------------
// h fp16 single-plane, K-blocked swizzled, TRIPLE buffered: [buf][kc][row][64]
__device__ __align__(128) __half g_hA[3][8][256][64];
// x fp16 single-plane per-step K-blocked swizzled: [t][row][64]
__device__ __align__(128) __half g_xA[T_][256][64];
__device__ unsigned g_flag[T_ + 1][8];   // readiness of input chunk kc at step t
__device__ unsigned g_count, g_gen;

// ---------------- math helpers ----------------
__device__ __forceinline__ float softplus_(float r) {
    return (r > 15.f) ? r : log1pf(expf(r));
}
__device__ __forceinline__ float sample_(float mu, float rho, float eps) {
    return mu + softplus_(rho) * eps;
}
__device__ __forceinline__ float sigmoid_(float x) {
    return __fdividef(1.f, 1.f + __expf(-x));
}
__device__ __forceinline__ float tanh_(float x) {
    return __fdividef(2.f, 1.f + __expf(-2.f * x)) - 1.f;
}

// ---------------- PTX helpers ----------------
__device__ __forceinline__ uint32_t smem_u32_(const void* p) {
    uint32_t a;
    asm("{ .reg .u64 t; cvta.to.shared.u64 t, %1; cvt.u32.u64 %0, t; }"
        : "=r"(a) : "l"(p));
    return a;
}
__device__ __forceinline__ void mbar_init_(uint32_t a, uint32_t cnt) {
    asm volatile("mbarrier.init.shared.b64 [%0], %1;" :: "r"(a), "r"(cnt) : "memory");
}
__device__ __forceinline__ void mbar_inval_(uint32_t a) {
    asm volatile("mbarrier.inval.shared.b64 [%0];" :: "r"(a) : "memory");
}
__device__ __forceinline__ void mbar_expect_tx_(uint32_t a, uint32_t bytes) {
    asm volatile("mbarrier.arrive.expect_tx.shared.b64 _, [%0], %1;"
                 :: "r"(a), "r"(bytes) : "memory");
}
__device__ __forceinline__ void mbar_arrive_(uint32_t a) {
    asm volatile("mbarrier.arrive.shared.b64 _, [%0];" :: "r"(a) : "memory");
}
__device__ __forceinline__ void mbar_wait_(uint32_t a, uint32_t parity) {
    uint32_t done;
    asm volatile(
        "{\n\t.reg .pred p;\n\t"
        "mbarrier.try_wait.parity.acquire.cta.shared::cta.b64 p, [%1], %2;\n\t"
        "selp.b32 %0, 1, 0, p;\n\t}"
        : "=r"(done) : "r"(a), "r"(parity) : "memory");
    if (!done) {
        asm volatile(
            "{\n\t.reg .pred P1;\n\t"
            "W_%=:\n\t"
            "mbarrier.try_wait.parity.acquire.cta.shared::cta.b64 P1, [%0], %1, 0x989680;\n\t"
            "@P1 bra.uni D_%=;\n\t"
            "bra.uni W_%=;\n\t"
            "D_%=:\n\t}"
            :: "r"(a), "r"(parity) : "memory");
    }
}
__device__ __forceinline__ void bulk_g2s_(uint32_t dst, const void* src,
                                          uint32_t bytes, uint32_t mbar) {
    asm volatile(
        "cp.async.bulk.shared::cluster.global.mbarrier::complete_tx::bytes "
        "[%0], [%1], %2, [%3];"
        :: "r"(dst), "l"(src), "r"(bytes), "r"(mbar) : "memory");
}
// IMPORTANT: the __nanosleep in this spin is load-bearing for correctness
// (R11/R13 removed it and silently corrupted; R8/R12/R14/R15 kept it, passed).
__device__ __forceinline__ void flag_wait_(const unsigned* p) {
    unsigned v;
    do {
        asm volatile("ld.global.cg.u32 %0, [%1];" : "=r"(v) : "l"(p));
        if (v >= FLAGTGT) break;
        __nanosleep(16);
    } while (1);
    __threadfence();
}

#define LDM4(R, A) \
    asm volatile("ldmatrix.sync.aligned.m8n8.x4.shared.b16 {%0,%1,%2,%3}, [%4];" \
        : "=r"((R)[0]), "=r"((R)[1]), "=r"((R)[2]), "=r"((R)[3]) : "r"(A))

#define MMA(Cf, Af, Bf0, Bf1) \
    asm volatile("mma.sync.aligned.m16n8k16.row.col.f32.f16.f16.f32 " \
        "{%0,%1,%2,%3}, {%4,%5,%6,%7}, {%8,%9}, {%0,%1,%2,%3};" \
        : "+f"((Cf)[0]), "+f"((Cf)[1]), "+f"((Cf)[2]), "+f"((Cf)[3]) \
        : "r"((Af)[0]), "r"((Af)[1]), "r"((Af)[2]), "r"((Af)[3]), \
          "r"(Bf0), "r"(Bf1))

extern "C" __global__ void bar_init_kernel() {
    const int tid = threadIdx.x;
    unsigned* f = (unsigned*)g_flag;
    for (int i = tid; i < (T_ + 1) * 8; i += blockDim.x)
        f[i] = (i < 8) ? FLAGTGT : 0u;     // step-0 input (zeros) pre-ready
    if (tid == 0) { g_count = 0; g_gen = 0; }
}

// ---------------- one-shot grid barrier (startup only) ----------------
__device__ __forceinline__ void grid_sync_(unsigned target) {
    __syncthreads();
    if (threadIdx.x == 0) {
        __threadfence();
        unsigned a = atomicAdd(&g_count, 1u);
        if (a == NCTA - 1) {
            g_count = 0;
            __threadfence();
            atomicExch(&g_gen, target);
        } else {
            unsigned g;
            do {
                asm volatile("ld.global.cg.u32 %0, [%1];" : "=r"(g) : "l"(&g_gen));
                if (g >= target) break;
                __nanosleep(32);
            } while (1);
        }
        __threadfence();
    }
    __syncthreads();
}

// gate/hcol mapping within the 16 local cols (4 gates x 4 h-cols, no shuffles)
__device__ __forceinline__ int colmap_(int n, int j0) {
    int gate = ((n >> 3) << 1) | (n & 1);
    int hcol = (n >> 1) & 3;
    return gate * H_ + j0 + hcol;
}

// ---------------- main persistent kernel ----------------
extern "C" __global__ void __launch_bounds__(NTHR, 1)
lstm_hmma(const float* __restrict__ x,
          const float* __restrict__ wih_mu, const float* __restrict__ wih_rho,
          const float* __restrict__ wih_eps,
          const float* __restrict__ whh_mu, const float* __restrict__ whh_rho,
          const float* __restrict__ whh_eps,
          const float* __restrict__ b_mu,   const float* __restrict__ b_rho,
          const float* __restrict__ b_eps,
          const float* __restrict__ lin_w,  const float* __restrict__ lin_b,
          float* __restrict__ out)
{
    extern __shared__ char smem[];
    const uint32_t sbase = smem_u32_(smem);
    float* bias_s = (float*)(smem + SM_BIAS);

    const int tid  = threadIdx.x;
    const int lane = tid & 31;
    const int w    = tid >> 5;          // 0..15 compute, 16 producer
    const int cta  = blockIdx.x;
    const int j0   = cta * HC;          // first h-col
    const int kc0  = j0 >> 6;           // h chunk our cols land in

    if (tid == 0) {
        #pragma unroll
        for (int s = 0; s < RD; s++) {
            mbar_init_(sbase + SM_MBF + s * 8, 1);
            mbar_init_(sbase + SM_MBE + s * 8, NCW);
        }
    }

    // ---- sample W into SMEM B planes (fp16 hi + lo, both used) ----
    for (int idx = tid; idx < NCOL * 576; idx += NTHR) {
        int n = idx / 576, k = idx - n * 576;
        int col = colmap_(n, j0);
        float wv;
        if (k < 512) {
            int gi = k * G_ + col;
            wv = sample_(whh_mu[gi], whh_rho[gi], whh_eps[gi]);
        } else {
            int gi = (k - 512) * G_ + col;
            wv = sample_(wih_mu[gi], wih_rho[gi], wih_eps[gi]);
        }
        __half hi = __float2half(wv);
        __half lo = __float2half(wv - __half2float(hi));
        *(__half*)(smem + SM_B + 0 * BPLANE + n * BROW + k * 2) = hi;
        *(__half*)(smem + SM_B + 1 * BPLANE + n * BROW + k * 2) = lo;
    }
    if (tid < NCOL) {
        int col = colmap_(tid, j0);
        bias_s[tid] = sample_(b_mu[col], b_rho[col], b_eps[col]);
    }

    // ---- build swizzled fp16 x plane + zero h buf0 (grid-wide striped) ----
    {
        const int gtid = cta * NTHR + tid;
        const int gn = NCTA * NTHR;
        for (int i = gtid; i < B_ * T_ * D_; i += gn) {
            int d = i & 63, r = i >> 6;
            int t = r & 511, b = r >> 9;            // x is [b][t][d]
            float v = __ldg(&x[i]);
            uint32_t off = ((uint32_t)t * 256 + (uint32_t)b) * 128 +
                           (((uint32_t)d * 2) ^ (((uint32_t)b & 7) << 4));
            *(__half*)((char*)g_xA + off) = __float2half(v);
        }
        uint32_t* hz = (uint32_t*)g_hA;             // buf0: 262144 B
        for (int i = gtid; i < 65536; i += gn) hz[i] = 0u;
    }

    grid_sync_(1);

    // ================= producer warp: lane s owns ring slot s =================
    // 9 items/step: item 0 = x chunk (no flag), items 1..8 = h chunk kc=item-1.
    if (w == NCW) {
        if (lane < RD) {
            const uint32_t mbf = sbase + SM_MBF + lane * 8;
            const uint32_t mbe = sbase + SM_MBE + lane * 8;
            const uint32_t dst = sbase + SM_A + (uint32_t)lane * 32768u;
            int ep = 1;                 // fresh barrier: parity-1 wait passes
            #pragma unroll 1
            for (unsigned itg = (unsigned)lane; itg < 9u * T_; itg += RD) {
                const int t = (int)(itg / 9u);
                const int item = (int)(itg % 9u);
                mbar_wait_(mbe, (uint32_t)ep); ep ^= 1;
                const char* src;
                if (item == 0) {
                    src = (const char*)g_xA + (size_t)t * 32768;
                } else {
                    const int kc = item - 1;
                    flag_wait_(&g_flag[t][kc]);
                    src = (const char*)g_hA + ((size_t)(t % 3) * 8 + kc) * 32768;
                }
                mbar_expect_tx_(mbf, 32768u);
                bulk_g2s_(dst, src, 32768u, mbf);
            }
        }
    } else {
        // ====== compute warps: warp w owns rows w*16..+16, all 16 cols ========
        const uint32_t akey = ((uint32_t)(lane & 7)) << 4;
        const uint32_t arow = (uint32_t)(w * 16 + (lane & 15)) * 128;
        uint32_t asw[4];
        #pragma unroll
        for (int ks = 0; ks < 4; ks++)
            asw[ks] = ((uint32_t)(ks * 32 + ((lane >> 4) * 16))) ^ akey;
        uint32_t bo;
        {
            uint32_t nrow = (uint32_t)(((lane >> 4) << 3) + (lane & 7));
            bo = nrow * BROW + ((uint32_t)((lane >> 3) & 1)) * 16;
        }

        float cst[2] = {0.f, 0.f};      // c-state: rows r, r+8 (one hcol/lane)

        int fp[RD] = {0, 0, 0, 0};
        unsigned itg = 0;
        const int L  = lane & 3;                 // local h-col
        const int u0 = (j0 & 63) + L;            // col within 64-col chunk

        #pragma unroll 1
        for (int t = 0; t < T_; t++) {
            float C[2][4];
            #pragma unroll
            for (int n = 0; n < 2; n++)
                #pragma unroll
                for (int q = 0; q < 4; q++) C[n][q] = 0.f;

            #pragma unroll 1
            for (int item = 0; item < 9; item++) {
                const int s = (int)(itg & (RD - 1)); itg++;
                mbar_wait_(sbase + SM_MBF + s * 8, (uint32_t)fp[s]); fp[s] ^= 1;
                const uint32_t a0 = sbase + SM_A + (uint32_t)s * 32768u;
                const uint32_t koff = (item == 0) ? 8u : (uint32_t)(item - 1);
                const uint32_t bb = sbase + SM_B + koff * 128u;

                // hoist ALL fragment loads, then free the slot early
                uint32_t Ah[4][4], Bh[4][4], Bl[4][4];
                #pragma unroll
                for (int ks = 0; ks < 4; ks++) {
                    LDM4(Ah[ks], a0 + arow + asw[ks]);
                    LDM4(Bh[ks], bb + bo + ks * 32);
                    LDM4(Bl[ks], bb + BPLANE + bo + ks * 32);
                }
                if (lane == 0) mbar_arrive_(sbase + SM_MBE + s * 8);

                #pragma unroll
                for (int ks = 0; ks < 4; ks++) {
                    MMA(C[0], Ah[ks], Bh[ks][0], Bh[ks][1]);
                    MMA(C[1], Ah[ks], Bh[ks][2], Bh[ks][3]);
                    MMA(C[0], Ah[ks], Bl[ks][0], Bl[ks][1]);
                    MMA(C[1], Ah[ks], Bl[ks][2], Bl[ks][3]);
                }
            }

            // ---- epilogue: gates, write fp16 h to buf (t+1)%3, publish flag ----
            {
                const int nbuf = (t + 1) % 3;
                char* hb = (char*)g_hA + ((size_t)nbuf * 8 + kc0) * 32768;
                #pragma unroll
                for (int rr = 0; rr < 2; rr++) {
                    const int r = w * 16 + (lane >> 2) + rr * 8;
                    const int c = rr * 2;
                    float iv = sigmoid_(C[0][c]     + bias_s[2 * L]);
                    float fv = sigmoid_(C[0][c + 1] + bias_s[2 * L + 1]);
                    float gv = tanh_   (C[1][c]     + bias_s[8 + 2 * L]);
                    float ov = sigmoid_(C[1][c + 1] + bias_s[8 + 2 * L + 1]);
                    cst[rr] = fv * cst[rr] + iv * gv;
                    float hval = ov * tanh_(cst[rr]);
                    uint32_t off = (uint32_t)r * 128 +
                                   (((uint32_t)u0 * 2) ^ (((uint32_t)r & 7) << 4));
                    *(__half*)(hb + off) = __float2half(hval);
                }
            }
            __threadfence();
            asm volatile("bar.sync 1, 512;" ::: "memory");  // compute warps only
            if (tid == 0) atomicAdd(&g_flag[t + 1][kc0], 1u);
        }

        // ---- final linear: h_last = input of step 512 -> buf 512%3 = 2 ----
        if (cta == 0) {
            if (tid == 0) {
                #pragma unroll
                for (int kc = 0; kc < 8; kc++) flag_wait_(&g_flag[T_][kc]);
            }
            asm volatile("bar.sync 1, 512;" ::: "memory");
            if (tid < B_) {
                const int b = tid;
                float s = 0.f;
                const char* hbase = (const char*)g_hA + (size_t)2 * 262144;
                #pragma unroll 4
                for (int j = 0; j < H_; j++) {
                    uint32_t off =
                        (((uint32_t)(j >> 6)) * 256 + (uint32_t)b) * 128 +
                        (((uint32_t)(j & 63) * 2) ^ (((uint32_t)b & 7) << 4));
                    float hv = __half2float(*(const __half*)(hbase + off));
                    s += hv * __ldg(&lin_w[j]);
                }
                out[b] = s + __ldg(&lin_b[0]);
            }
        }
    }

    __syncthreads();
    if (tid == 0) {
        #pragma unroll
        for (int s = 0; s < RD; s++) {
            mbar_inval_(sbase + SM_MBF + s * 8);
            mbar_inval_(sbase + SM_MBE + s * 8);
        }
    }
}

// ---------------- launch ----------------
extern "C" void kernel_launch(void* const* d_in, const int* in_sizes, int n_in,
                              void* d_out, int out_size)
{
    const float* x       = (const float*)d_in[0];
    const float* wih_mu  = (const float*)d_in[1];
    const float* wih_rho = (const float*)d_in[2];
    const float* wih_eps = (const float*)d_in[3];
    const float* whh_mu  = (const float*)d_in[4];
    const float* whh_rho = (const float*)d_in[5];
    const float* whh_eps = (const float*)d_in[6];
    const float* b_mu    = (const float*)d_in[7];
    const float* b_rho   = (const float*)d_in[8];
    const float* b_eps   = (const float*)d_in[9];
    const float* lin_w   = (const float*)d_in[10];
    const float* lin_b   = (const float*)d_in[11];
    float* out = (float*)d_out;

    static int inited = 0;
    if (!inited) {
        cudaFuncSetAttribute(lstm_hmma,
                             cudaFuncAttributeMaxDynamicSharedMemorySize, SMEM_BYTES);
        inited = 1;
    }

    bar_init_kernel<<<1, 256>>>();
    lstm_hmma<<<NCTA, NTHR, SMEM_BYTES>>>(x,
                                          wih_mu, wih_rho, wih_eps,
                                          whh_mu, whh_rho, whh_eps,
                                          b_mu, b_rho, b_eps,
                                          lin_w, lin_b, out);
}